// round 7
// baseline (speedup 1.0000x reference)
#include <cuda_runtime.h>

#define NFFT    1024
#define FREQ    513
#define FRAMES  2048
#define BATCH   16
#define HOP     256
#define PAD     384
#define OUTLEN  524288          // (2047*256 + 1024) - 2*384 == 2^19
#define FPB     8               // frames per block
#define XPITCH  576             // per-frame pitch (floats) for exchange arrays
#define OPITCH  520             // per-frame pitch for even/odd OLA arrays (>=512)
#define BPB     256             // blocks per batch (2048/8)
#define HALO    768
#define NZERO   (BATCH * 257 * HALO)

__device__ float2 g_tw[1024];   // e^{+2*pi*i*j/1024}

__device__ __forceinline__ float2 cadd(float2 a, float2 b){return make_float2(a.x+b.x, a.y+b.y);}
__device__ __forceinline__ float2 csub(float2 a, float2 b){return make_float2(a.x-b.x, a.y-b.y);}
__device__ __forceinline__ float2 cmul(float2 a, float2 b){
    return make_float2(fmaf(a.x, b.x, -a.y*b.y), fmaf(a.x, b.y, a.y*b.x));
}
__device__ __forceinline__ float2 mul_i(float2 a){return make_float2(-a.y, a.x);}

// In-place 8-point inverse DFT: y[n] = sum_m v[m] e^{+2*pi*i*m*n/8}
__device__ __forceinline__ void ifft8(float2* v){
    float2 e2a = cadd(v[0], v[4]);
    float2 e2b = csub(v[0], v[4]);
    float2 o2a = cadd(v[2], v[6]);
    float2 o2b = csub(v[2], v[6]);
    float2 E0 = cadd(e2a, o2a);
    float2 E2 = csub(e2a, o2a);
    float2 io2b = mul_i(o2b);
    float2 E1 = cadd(e2b, io2b);
    float2 E3 = csub(e2b, io2b);
    float2 p2a = cadd(v[1], v[5]);
    float2 p2b = csub(v[1], v[5]);
    float2 q2a = cadd(v[3], v[7]);
    float2 q2b = csub(v[3], v[7]);
    float2 O0 = cadd(p2a, q2a);
    float2 O2 = csub(p2a, q2a);
    float2 iq2b = mul_i(q2b);
    float2 O1 = cadd(p2b, iq2b);
    float2 O3 = csub(p2b, iq2b);
    const float C = 0.70710678118654752440f;
    float2 w1O1 = make_float2(C*(O1.x - O1.y),  C*(O1.x + O1.y));
    float2 w3O3 = make_float2(-C*(O3.x + O3.y), C*(O3.x - O3.y));
    float2 iO2  = mul_i(O2);
    v[0]=cadd(E0,O0);   v[4]=csub(E0,O0);
    v[1]=cadd(E1,w1O1); v[5]=csub(E1,w1O1);
    v[2]=cadd(E2,iO2);  v[6]=csub(E2,iO2);
    v[3]=cadd(E3,w3O3); v[7]=csub(E3,w3O3);
}

// Apply w^1..w^7 to v[1..7] via register power chain.
__device__ __forceinline__ void apply_twiddle_chain(float2* v, float2 w1){
    float2 w2 = cmul(w1, w1);
    float2 w3 = cmul(w2, w1);
    float2 w4 = cmul(w2, w2);
    float2 w5 = cmul(w3, w2);
    float2 w6 = cmul(w3, w3);
    float2 w7 = cmul(w4, w3);
    v[1] = cmul(v[1], w1);
    v[2] = cmul(v[2], w2);
    v[3] = cmul(v[3], w3);
    v[4] = cmul(v[4], w4);
    v[5] = cmul(v[5], w5);
    v[6] = cmul(v[6], w6);
    v[7] = cmul(v[7], w7);
}

// ---------------------------------------------------------------------------
// Prep kernel: build twiddle table AND zero the halo windows of the output.
// ---------------------------------------------------------------------------
__global__ __launch_bounds__(256) void prep_kernel(float* __restrict__ out){
    const int idx = blockIdx.x * 256 + threadIdx.x;
    if (idx < 1024) {
        float s, c;
        sincosf((float)idx * 6.13592315154256491887e-3f, &s, &c); // 2*pi/1024
        g_tw[idx] = make_float2(c, s);
    }
    if (idx < NZERO) {
        const int i   = idx % HALO;
        const int reg = idx / HALO;
        const int b   = reg / 257;
        const int p   = reg % 257;
        const int n   = p * 2048 + i;
        const int o   = n - PAD;
        if (o >= 0 && o < OUTLEN)
            out[(size_t)b * OUTLEN + o] = 0.0f;
    }
}

// ---------------------------------------------------------------------------
// Fused kernel: packed real inverse FFT (radix-8^3 on 512-pt complex),
// window, in-smem overlap-add. ALL smem traffic is 32-bit and bank-conflict
// free (split re/im exchange arrays, split even/odd OLA arrays with +16
// bank skew on the odd array). 512 threads = 8 frames x 64 threads.
// ---------------------------------------------------------------------------
__global__ __launch_bounds__(512) void istft_fused_kernel(
    const float* __restrict__ sre,
    const float* __restrict__ sim,
    const float* __restrict__ win,
    float* __restrict__ out)
{
    __shared__ float ctwR1[64], ctwI1[64];   // e^{+2pi i t/1024}
    __shared__ float ctwR2[8],  ctwI2[8];    // e^{+2pi i a/64}
    __shared__ float ctwR3[64], ctwI3[64];   // e^{+2pi i t/512}
    __shared__ float pool[2 * FPB * XPITCH]; // sR | sI; later frb_e | frb_o

    float* const sR = pool;
    float* const sI = pool + FPB * XPITCH;

    const int tid = threadIdx.x;

    if (tid < 64) {
        float2 w = g_tw[tid];     ctwR1[tid] = w.x; ctwI1[tid] = w.y;
        float2 u = g_tw[2 * tid]; ctwR3[tid] = u.x; ctwI3[tid] = u.y;
        if (tid < 8) { float2 z = g_tw[16 * tid]; ctwR2[tid] = z.x; ctwI2[tid] = z.y; }
    }

    // ---- Load spectrum, frame-coalesced (8 consecutive frames / block) -----
    const int gf0 = blockIdx.x * FPB;
    const int b   = gf0 >> 11;               // batch
    const int p   = blockIdx.x & (BPB - 1);  // block within batch
    const int fr  = gf0 & (FRAMES - 1);
    const size_t specbase = (size_t)b * FREQ * FRAMES + fr;
    {
        const int k = tid;              // bins 0..511
        const float4* pr = (const float4*)(sre + specbase + (size_t)k * FRAMES);
        const float4* pi = (const float4*)(sim + specbase + (size_t)k * FRAMES);
        float4 r0 = pr[0], r1 = pr[1];
        float4 i0 = pi[0], i1 = pi[1];
        float re[8] = {r0.x, r0.y, r0.z, r0.w, r1.x, r1.y, r1.z, r1.w};
        float im[8] = {i0.x, i0.y, i0.z, i0.w, i1.x, i1.y, i1.z, i1.w};
        if (k == 0) { im[0]=im[1]=im[2]=im[3]=im[4]=im[5]=im[6]=im[7]=0.0f; }
#pragma unroll
        for (int f = 0; f < FPB; f++) {
            sR[f * XPITCH + k] = re[f];
            sI[f * XPITCH + k] = im[f];
        }
    }
    if (tid == 0) {                     // Nyquist bin 512, imag dropped
        const float4* pr = (const float4*)(sre + specbase + (size_t)512 * FRAMES);
        float4 r0 = pr[0], r1 = pr[1];
        float re[8] = {r0.x, r0.y, r0.z, r0.w, r1.x, r1.y, r1.z, r1.w};
#pragma unroll
        for (int f = 0; f < FPB; f++) {
            sR[f * XPITCH + 512] = re[f];
            sI[f * XPITCH + 512] = 0.0f;
        }
    }
    __syncthreads();

    const int f = tid >> 6;             // frame within block
    const int t = tid & 63;             // lane within frame
    float* const fR = sR + f * XPITCH;
    float* const fI = sI + f * XPITCH;

    // ---- Pack: Z[k] = (S[k]+conj(S[512-k])) + i*w^k*(S[k]-conj(S[512-k])) --
    float2 v[8];
    {
        const float wtr = ctwR1[t], wti = ctwI1[t];
        const float C16R[8] = { 1.0f, 0.92387953251128674f, 0.70710678118654752f,
                                0.38268343236508977f, 0.0f, -0.38268343236508977f,
                               -0.70710678118654752f, -0.92387953251128674f };
        const float C16I[8] = { 0.0f, 0.38268343236508977f, 0.70710678118654752f,
                                0.92387953251128674f, 1.0f, 0.92387953251128674f,
                                0.70710678118654752f, 0.38268343236508977f };
#pragma unroll
        for (int g = 0; g < 8; g++) {
            const int k = t + 64 * g;
            float Ar = fR[k],        Ai = fI[k];
            float Br = fR[512 - k],  Bi = fI[512 - k];
            float Ur = Ar + Br, Ui = Ai - Bi;
            float Vr = Ar - Br, Vi = Ai + Bi;
            float wr = wtr * C16R[g] - wti * C16I[g];
            float wi = wtr * C16I[g] + wti * C16R[g];
            v[g] = make_float2(Ur - wr*Vi - wi*Vr,
                               Ui + wr*Vr - wi*Vi);
        }
    }
    __syncthreads();

    // ---- Stage 1: store at t + 72a (banks = t, conflict-free) --------------
    ifft8(v);
#pragma unroll
    for (int a = 0; a < 8; a++) {
        fR[t + 72 * a] = v[a].x;
        fI[t + 72 * a] = v[a].y;
    }
    __syncthreads();

    // ---- Stage 2: load alpha+8be+72a (banks alpha+8a), twiddle, ifft8,
    //               store a+8bb+68alpha (banks a+4alpha) --------------------
    {
        const int alpha = t & 7, a = t >> 3;
#pragma unroll
        for (int be = 0; be < 8; be++) {
            const int idx = alpha + 8 * be + 72 * a;
            v[be] = make_float2(fR[idx], fI[idx]);
        }
        apply_twiddle_chain(v, make_float2(ctwR2[a], ctwI2[a]));
        __syncthreads();
        ifft8(v);
#pragma unroll
        for (int bb = 0; bb < 8; bb++) {
            const int idx = a + 8 * bb + 68 * alpha;
            fR[idx] = v[bb].x;
            fI[idx] = v[bb].y;
        }
    }
    __syncthreads();

    // ---- Stage 3: load t + 68alpha (banks t+4alpha), twiddle, ifft8 -------
    {
#pragma unroll
        for (int al = 0; al < 8; al++) {
            const int idx = t + 68 * al;
            v[al] = make_float2(fR[idx], fI[idx]);
        }
        apply_twiddle_chain(v, make_float2(ctwR3[t], ctwI3[t]));
        ifft8(v);          // v[c] = 1024 * z[t + 64c]
    }
    __syncthreads();       // all stage-3 smem reads done; pool reusable

    // ---- Unpack + window into split even/odd OLA arrays --------------------
    // sample 2n (even) = v.x -> frb_e[n]; sample 2n+1 (odd) = v.y -> frb_o[n]
    // frb_o skewed +16 floats so paired even/odd lanes hit disjoint banks.
    float* const frb_e = pool;
    float* const frb_o = pool + FPB * OPITCH + 16;
#pragma unroll
    for (int c = 0; c < 8; c++) {
        const int n = t + 64 * c;                   // 0..511
        float2 w2 = *(const float2*)(win + 2 * n);
        frb_e[f * OPITCH + n] = v[c].x * w2.x * (1.0f / 1024.0f);
        frb_o[f * OPITCH + n] = v[c].y * w2.y * (1.0f / 1024.0f);
    }
    __syncthreads();

    // ---- In-smem overlap-add over the block's 8 frames ---------------------
    // All 4 taps of sample j share parity (offsets differ by 256).
    const float ENV_INV = 2.0f / 3.0f;
    float* outb = out + (size_t)b * OUTLEN;
    const int nbase = p * 2048;
#pragma unroll 1
    for (int j = tid; j < 2816; j += 512) {
        int fhi = j >> 8;         if (fhi > 7) fhi = 7;
        int flo = (j - 768) >> 8; if (flo < 0) flo = 0;
        const float* fa = (j & 1) ? frb_o : frb_e;
        float acc = 0.0f;
        for (int m = flo; m <= fhi; m++)
            acc += fa[m * OPITCH + ((j - (m << 8)) >> 1)];

        const int n = nbase + j;
        const int o = n - PAD;
        if (j >= 768 && j < 2048) {
            outb[o] = acc * ENV_INV;
        } else {
            int Mhi = n >> 8;         if (Mhi > FRAMES - 1) Mhi = FRAMES - 1;
            int Mlo = (n - 768) >> 8; if (Mlo < 0) Mlo = 0;
            float env = 0.0f;
            for (int m = Mlo; m <= Mhi; m++) {
                const float w = win[n - (m << 8)];
                env += w * w;
            }
            if (o >= 0 && o < OUTLEN)
                atomicAdd(&outb[o], acc / env);
        }
    }
}

// ---------------------------------------------------------------------------
extern "C" void kernel_launch(void* const* d_in, const int* in_sizes, int n_in,
                              void* d_out, int out_size)
{
    const float* sre = (const float*)d_in[0];
    const float* sim = (const float*)d_in[1];
    const float* win = (const float*)d_in[2];
    float* out = (float*)d_out;

    prep_kernel<<<(NZERO + 255) / 256, 256>>>(out);
    istft_fused_kernel<<<BATCH * FRAMES / FPB, 512>>>(sre, sim, win, out);
}

// round 8
// speedup vs baseline: 1.2077x; 1.2077x over previous
#include <cuda_runtime.h>

#define NFFT    1024
#define FREQ    513
#define FRAMES  2048
#define BATCH   16
#define HOP     256
#define PAD     384
#define OUTLEN  524288          // (2047*256 + 1024) - 2*384 == 2^19
#define FPB     16              // frames per block
#define FPITCH  569             // per-frame smem pitch (float2), ODD for loader banks
#define BPB     128             // blocks per batch (2048/16)
#define SPAN    4096            // samples advanced per block (FPB*HOP)
#define HALO    768
#define NWIN    (BATCH * (BPB + 1))    // halo windows to zero

__device__ float2 g_tw[1024];   // e^{+2*pi*i*j/1024}

__device__ __forceinline__ float2 cadd(float2 a, float2 b){return make_float2(a.x+b.x, a.y+b.y);}
__device__ __forceinline__ float2 csub(float2 a, float2 b){return make_float2(a.x-b.x, a.y-b.y);}
__device__ __forceinline__ float2 cmul(float2 a, float2 b){
    return make_float2(fmaf(a.x, b.x, -a.y*b.y), fmaf(a.x, b.y, a.y*b.x));
}
__device__ __forceinline__ float2 mul_i(float2 a){return make_float2(-a.y, a.x);}

// In-place 8-point inverse DFT: y[n] = sum_m v[m] e^{+2*pi*i*m*n/8}
__device__ __forceinline__ void ifft8(float2* v){
    float2 e2a = cadd(v[0], v[4]);
    float2 e2b = csub(v[0], v[4]);
    float2 o2a = cadd(v[2], v[6]);
    float2 o2b = csub(v[2], v[6]);
    float2 E0 = cadd(e2a, o2a);
    float2 E2 = csub(e2a, o2a);
    float2 io2b = mul_i(o2b);
    float2 E1 = cadd(e2b, io2b);
    float2 E3 = csub(e2b, io2b);
    float2 p2a = cadd(v[1], v[5]);
    float2 p2b = csub(v[1], v[5]);
    float2 q2a = cadd(v[3], v[7]);
    float2 q2b = csub(v[3], v[7]);
    float2 O0 = cadd(p2a, q2a);
    float2 O2 = csub(p2a, q2a);
    float2 iq2b = mul_i(q2b);
    float2 O1 = cadd(p2b, iq2b);
    float2 O3 = csub(p2b, iq2b);
    const float C = 0.70710678118654752440f;
    float2 w1O1 = make_float2(C*(O1.x - O1.y),  C*(O1.x + O1.y));
    float2 w3O3 = make_float2(-C*(O3.x + O3.y), C*(O3.x - O3.y));
    float2 iO2  = mul_i(O2);
    v[0]=cadd(E0,O0);   v[4]=csub(E0,O0);
    v[1]=cadd(E1,w1O1); v[5]=csub(E1,w1O1);
    v[2]=cadd(E2,iO2);  v[6]=csub(E2,iO2);
    v[3]=cadd(E3,w3O3); v[7]=csub(E3,w3O3);
}

// Apply w^1..w^7 to v[1..7] via register power chain.
__device__ __forceinline__ void apply_twiddle_chain(float2* v, float2 w1){
    float2 w2 = cmul(w1, w1);
    float2 w3 = cmul(w2, w1);
    float2 w4 = cmul(w2, w2);
    float2 w5 = cmul(w3, w2);
    float2 w6 = cmul(w3, w3);
    float2 w7 = cmul(w4, w3);
    v[1] = cmul(v[1], w1);
    v[2] = cmul(v[2], w2);
    v[3] = cmul(v[3], w3);
    v[4] = cmul(v[4], w4);
    v[5] = cmul(v[5], w5);
    v[6] = cmul(v[6], w6);
    v[7] = cmul(v[7], w7);
}

// ---------------------------------------------------------------------------
// Prep kernel: one block zeroes one 768-float halo window (192 float4 stores).
// Block 0 additionally builds the twiddle table.
// ---------------------------------------------------------------------------
__global__ __launch_bounds__(192) void prep_kernel(float* __restrict__ out){
    const int r = blockIdx.x;                 // 0 .. NWIN-1
    if (r == 0) {
        for (int j = threadIdx.x; j < 1024; j += 192) {
            float s, c;
            sincosf((float)j * 6.13592315154256491887e-3f, &s, &c); // 2*pi/1024
            g_tw[j] = make_float2(c, s);
        }
    }
    const int b = r / (BPB + 1);
    const int p = r % (BPB + 1);
    // window covers o in [p*SPAN - PAD, p*SPAN + PAD), clamped to [0, OUTLEN)
    const int o4start = (p * SPAN - PAD) >> 2;          // float4 index (may be <0)
    const int o4 = o4start + threadIdx.x;
    if (o4 >= 0 && o4 < OUTLEN / 4) {
        float4* dst = (float4*)(out + (size_t)b * OUTLEN);
        dst[o4] = make_float4(0.f, 0.f, 0.f, 0.f);
    }
}

// ---------------------------------------------------------------------------
// Fused kernel: packed real inverse FFT (radix-8^3 on 512-pt complex),
// window, in-smem overlap-add. 1024 threads = 16 frames x 64 threads.
// Interior (4-tap) samples: env == 1.5 EXACT -> direct store / scaled atomic.
// True env loop only at global batch edges.
// ---------------------------------------------------------------------------
__global__ __launch_bounds__(1024, 2) void istft_fused_kernel(
    const float* __restrict__ sre,
    const float* __restrict__ sim,
    const float* __restrict__ win,
    float* __restrict__ out)
{
    __shared__ float2 ctw1[64];         // e^{+2pi i t/1024}
    __shared__ float2 ctw2[8];          // e^{+2pi i a/64}
    __shared__ float2 ctw3[64];         // e^{+2pi i t/512}
    extern __shared__ float2 buf[];     // [FPB * FPITCH] float2; reused for OLA

    const int tid = threadIdx.x;

    if (tid < 64) {
        ctw1[tid] = g_tw[tid];
        ctw3[tid] = g_tw[2 * tid];
        if (tid < 8) ctw2[tid] = g_tw[16 * tid];
    }

    // ---- Load spectrum, frame-coalesced (16 consecutive frames / block) ----
    const int gf0 = blockIdx.x * FPB;
    const int b   = gf0 >> 11;               // batch
    const int p   = blockIdx.x & (BPB - 1);  // block within batch
    const int fr  = gf0 & (FRAMES - 1);
    const size_t specbase = (size_t)b * FREQ * FRAMES + fr;
    {
        const int k = tid >> 1;         // bin 0..511
        const int h = tid & 1;          // frame half: frames 8h..8h+7
        const float4* pr = (const float4*)(sre + specbase + (size_t)k * FRAMES) + 2 * h;
        const float4* pi = (const float4*)(sim + specbase + (size_t)k * FRAMES) + 2 * h;
        float4 r0 = pr[0], r1 = pr[1];
        float4 i0 = pi[0], i1 = pi[1];
        float re[8] = {r0.x, r0.y, r0.z, r0.w, r1.x, r1.y, r1.z, r1.w};
        float im[8] = {i0.x, i0.y, i0.z, i0.w, i1.x, i1.y, i1.z, i1.w};
        if (k == 0) { im[0]=im[1]=im[2]=im[3]=im[4]=im[5]=im[6]=im[7]=0.0f; }
#pragma unroll
        for (int q = 0; q < 8; q++)
            buf[(8 * h + q) * FPITCH + k] = make_float2(re[q], im[q]);
    }
    if (tid < 2) {                      // Nyquist bin 512, imag dropped
        const int h = tid;
        const float4* pr = (const float4*)(sre + specbase + (size_t)512 * FRAMES) + 2 * h;
        float4 r0 = pr[0], r1 = pr[1];
        float re[8] = {r0.x, r0.y, r0.z, r0.w, r1.x, r1.y, r1.z, r1.w};
#pragma unroll
        for (int q = 0; q < 8; q++)
            buf[(8 * h + q) * FPITCH + 512] = make_float2(re[q], 0.0f);
    }
    __syncthreads();

    const int f = tid >> 6;             // frame within block (0..15)
    const int t = tid & 63;             // lane within frame
    float2* const Bf = buf + f * FPITCH;

    // ---- Pack: Z[k] = (S[k]+conj(S[512-k])) + i*w^k*(S[k]-conj(S[512-k])) --
    float2 v[8];
    {
        const float2 wt = ctw1[t];
        const float C16R[8] = { 1.0f, 0.92387953251128674f, 0.70710678118654752f,
                                0.38268343236508977f, 0.0f, -0.38268343236508977f,
                               -0.70710678118654752f, -0.92387953251128674f };
        const float C16I[8] = { 0.0f, 0.38268343236508977f, 0.70710678118654752f,
                                0.92387953251128674f, 1.0f, 0.92387953251128674f,
                                0.70710678118654752f, 0.38268343236508977f };
#pragma unroll
        for (int g = 0; g < 8; g++) {
            const int k = t + 64 * g;
            float2 A  = Bf[k];
            float2 Bc = Bf[512 - k];
            float Ur = A.x + Bc.x, Ui = A.y - Bc.y;
            float Vr = A.x - Bc.x, Vi = A.y + Bc.y;
            float wr = wt.x * C16R[g] - wt.y * C16I[g];
            float wi = wt.x * C16I[g] + wt.y * C16R[g];
            v[g] = make_float2(Ur - wr*Vi - wi*Vr,
                               Ui + wr*Vr - wi*Vi);
        }
    }
    __syncthreads();

    // ---- Stage 1: store at t + 72a --------------------------------------
    ifft8(v);
#pragma unroll
    for (int a = 0; a < 8; a++)
        Bf[t + 72 * a] = v[a];
    __syncthreads();

    // ---- Stage 2: load alpha+8be+72a, twiddle, ifft8, store a+8bb+66alpha -
    {
        const int alpha = t & 7, a = t >> 3;
#pragma unroll
        for (int be = 0; be < 8; be++)
            v[be] = Bf[alpha + 8 * be + 72 * a];
        apply_twiddle_chain(v, ctw2[a]);        // w = e^{+2pi i a/64}
        __syncthreads();
        ifft8(v);
#pragma unroll
        for (int bb = 0; bb < 8; bb++)
            Bf[a + 8 * bb + 66 * alpha] = v[bb];
    }
    __syncthreads();

    // ---- Stage 3: load t + 66alpha, twiddle, ifft8 ------------------------
    {
#pragma unroll
        for (int al = 0; al < 8; al++)
            v[al] = Bf[t + 66 * al];
        apply_twiddle_chain(v, ctw3[t]);        // w = e^{+2pi i t/512}
        ifft8(v);          // v[c] = 1024 * z[t + 64c]
    }
    __syncthreads();       // all stage-3 smem reads done; buf reusable

    // ---- Unpack + window into smem frame buffer (pitch 1032 floats) --------
    float* const frb = (float*)buf;
#pragma unroll
    for (int c = 0; c < 8; c++) {
        const int n = t + 64 * c;                   // 0..511
        float2 w2 = *(const float2*)(win + 2 * n);
        *(float2*)(frb + f * 1032 + 2 * n) =
            make_float2(v[c].x * w2.x * (1.0f / 1024.0f),
                        v[c].y * w2.y * (1.0f / 1024.0f));
    }
    __syncthreads();

    // ---- In-smem overlap-add over the block's 16 frames --------------------
    // Block owns output positions [p*SPAN, p*SPAN+SPAN); local j in [0, 4864).
    // 4-tap positions (j in [768,4096) AND all interior-halo) have env==1.5
    // exactly; true env loop only at global batch edges.
    const float ENV_INV = 2.0f / 3.0f;
    float* outb = out + (size_t)b * OUTLEN;
    const int nbase = p * SPAN;
#pragma unroll 1
    for (int j = tid; j < SPAN + HALO; j += 1024) {
        int fhi = j >> 8;         if (fhi > FPB - 1) fhi = FPB - 1;
        int flo = (j - 768) >> 8; if (flo < 0) flo = 0;
        float acc = 0.0f;
        for (int m = flo; m <= fhi; m++)
            acc += frb[m * 1032 + j - (m << 8)];

        const int n = nbase + j;
        const int o = n - PAD;
        if (j >= HALO && j < SPAN) {
            outb[o] = acc * ENV_INV;            // interior: direct store
        } else if ((p == 0 && j < HALO) || (p == BPB - 1 && j >= SPAN)) {
            // true batch edge: compute env from the window
            int Mhi = n >> 8;         if (Mhi > FRAMES - 1) Mhi = FRAMES - 1;
            int Mlo = (n - 768) >> 8; if (Mlo < 0) Mlo = 0;
            float env = 0.0f;
            for (int m = Mlo; m <= Mhi; m++) {
                const float w = win[n - (m << 8)];
                env += w * w;
            }
            if (o >= 0 && o < OUTLEN)
                atomicAdd(&outb[o], acc / env);
        } else {
            // interior block boundary: still 4 taps globally -> env == 1.5
            atomicAdd(&outb[o], acc * ENV_INV);
        }
    }
}

// ---------------------------------------------------------------------------
extern "C" void kernel_launch(void* const* d_in, const int* in_sizes, int n_in,
                              void* d_out, int out_size)
{
    const float* sre = (const float*)d_in[0];
    const float* sim = (const float*)d_in[1];
    const float* win = (const float*)d_in[2];
    float* out = (float*)d_out;

    const int smem = FPB * FPITCH * (int)sizeof(float2);   // 72,832 B
    cudaFuncSetAttribute(istft_fused_kernel,
                         cudaFuncAttributeMaxDynamicSharedMemorySize, smem);

    prep_kernel<<<NWIN, 192>>>(out);
    istft_fused_kernel<<<BATCH * FRAMES / FPB, 1024, smem>>>(sre, sim, win, out);
}

// round 9
// speedup vs baseline: 1.3612x; 1.1270x over previous
#include <cuda_runtime.h>

#define NFFT    1024
#define FREQ    513
#define FRAMES  2048
#define BATCH   16
#define HOP     256
#define PAD     384
#define OUTLEN  524288          // (2047*256 + 1024) - 2*384 == 2^19
#define FPB     16              // frames per block
#define FPITCH  569             // per-frame smem pitch (float2)
#define BPB     128             // blocks per batch (2048/16)
#define SPAN    4096            // samples advanced per block (FPB*HOP)
#define HALO    768
#define NWIN    (BATCH * (BPB + 1))    // halo windows to zero

__device__ float2 g_tw[1024];   // e^{+2*pi*i*j/1024}

// Packed f32x2 add/sub (FADD2 path on sm_103a; bitwise identical to scalar).
__device__ __forceinline__ float2 cadd(float2 a, float2 b){
    float2 r;
    asm("add.rn.f32x2 %0, %1, %2;"
        : "=l"(reinterpret_cast<unsigned long long&>(r))
        : "l"(reinterpret_cast<const unsigned long long&>(a)),
          "l"(reinterpret_cast<const unsigned long long&>(b)));
    return r;
}
__device__ __forceinline__ float2 csub(float2 a, float2 b){
    float2 r;
    asm("sub.rn.f32x2 %0, %1, %2;"
        : "=l"(reinterpret_cast<unsigned long long&>(r))
        : "l"(reinterpret_cast<const unsigned long long&>(a)),
          "l"(reinterpret_cast<const unsigned long long&>(b)));
    return r;
}
__device__ __forceinline__ float2 cmul(float2 a, float2 b){
    return make_float2(fmaf(a.x, b.x, -a.y*b.y), fmaf(a.x, b.y, a.y*b.x));
}
__device__ __forceinline__ float2 mul_i(float2 a){return make_float2(-a.y, a.x);}

// In-place 8-point inverse DFT: y[n] = sum_m v[m] e^{+2*pi*i*m*n/8}
__device__ __forceinline__ void ifft8(float2* v){
    float2 e2a = cadd(v[0], v[4]);
    float2 e2b = csub(v[0], v[4]);
    float2 o2a = cadd(v[2], v[6]);
    float2 o2b = csub(v[2], v[6]);
    float2 E0 = cadd(e2a, o2a);
    float2 E2 = csub(e2a, o2a);
    float2 io2b = mul_i(o2b);
    float2 E1 = cadd(e2b, io2b);
    float2 E3 = csub(e2b, io2b);
    float2 p2a = cadd(v[1], v[5]);
    float2 p2b = csub(v[1], v[5]);
    float2 q2a = cadd(v[3], v[7]);
    float2 q2b = csub(v[3], v[7]);
    float2 O0 = cadd(p2a, q2a);
    float2 O2 = csub(p2a, q2a);
    float2 iq2b = mul_i(q2b);
    float2 O1 = cadd(p2b, iq2b);
    float2 O3 = csub(p2b, iq2b);
    const float C = 0.70710678118654752440f;
    float2 w1O1 = make_float2(C*(O1.x - O1.y),  C*(O1.x + O1.y));
    float2 w3O3 = make_float2(-C*(O3.x + O3.y), C*(O3.x - O3.y));
    float2 iO2  = mul_i(O2);
    v[0]=cadd(E0,O0);   v[4]=csub(E0,O0);
    v[1]=cadd(E1,w1O1); v[5]=csub(E1,w1O1);
    v[2]=cadd(E2,iO2);  v[6]=csub(E2,iO2);
    v[3]=cadd(E3,w3O3); v[7]=csub(E3,w3O3);
}

// Apply w^1..w^7 to v[1..7] via register power chain.
__device__ __forceinline__ void apply_twiddle_chain(float2* v, float2 w1){
    float2 w2 = cmul(w1, w1);
    float2 w3 = cmul(w2, w1);
    float2 w4 = cmul(w2, w2);
    float2 w5 = cmul(w3, w2);
    float2 w6 = cmul(w3, w3);
    float2 w7 = cmul(w4, w3);
    v[1] = cmul(v[1], w1);
    v[2] = cmul(v[2], w2);
    v[3] = cmul(v[3], w3);
    v[4] = cmul(v[4], w4);
    v[5] = cmul(v[5], w5);
    v[6] = cmul(v[6], w6);
    v[7] = cmul(v[7], w7);
}

// ---------------------------------------------------------------------------
// Prep kernel: one block zeroes one 768-float halo window (192 float4 stores).
// Block 0 additionally builds the twiddle table.
// ---------------------------------------------------------------------------
__global__ __launch_bounds__(192) void prep_kernel(float* __restrict__ out){
    const int r = blockIdx.x;                 // 0 .. NWIN-1
    if (r == 0) {
        for (int j = threadIdx.x; j < 1024; j += 192) {
            float s, c;
            sincosf((float)j * 6.13592315154256491887e-3f, &s, &c); // 2*pi/1024
            g_tw[j] = make_float2(c, s);
        }
    }
    const int b = r / (BPB + 1);
    const int p = r % (BPB + 1);
    const int o4start = (p * SPAN - PAD) >> 2;
    const int o4 = o4start + threadIdx.x;
    if (o4 >= 0 && o4 < OUTLEN / 4) {
        float4* dst = (float4*)(out + (size_t)b * OUTLEN);
        dst[o4] = make_float4(0.f, 0.f, 0.f, 0.f);
    }
}

// ---------------------------------------------------------------------------
// Fused kernel: packed real inverse FFT (radix-8^3 on 512-pt complex),
// window, in-smem overlap-add. 1024 threads = 16 frames x 64 threads.
// ---------------------------------------------------------------------------
__global__ __launch_bounds__(1024, 2) void istft_fused_kernel(
    const float* __restrict__ sre,
    const float* __restrict__ sim,
    const float* __restrict__ win,
    float* __restrict__ out)
{
    __shared__ float2 ctw1[64];         // e^{+2pi i t/1024}
    __shared__ float2 ctw2[8];          // e^{+2pi i a/64}
    __shared__ float2 ctw3[64];         // e^{+2pi i t/512}
    extern __shared__ float2 buf[];     // [FPB * FPITCH] float2; reused for OLA

    const int tid = threadIdx.x;

    if (tid < 64) {
        ctw1[tid] = g_tw[tid];
        ctw3[tid] = g_tw[2 * tid];
        if (tid < 8) ctw2[tid] = g_tw[16 * tid];
    }

    // ---- Load spectrum, frame-coalesced (16 consecutive frames / block) ----
    const int gf0 = blockIdx.x * FPB;
    const int b   = gf0 >> 11;               // batch
    const int p   = blockIdx.x & (BPB - 1);  // block within batch
    const int fr  = gf0 & (FRAMES - 1);
    const size_t specbase = (size_t)b * FREQ * FRAMES + fr;
    {
        const int k = tid >> 1;         // bin 0..511
        const int h = tid & 1;          // frame half: frames 8h..8h+7
        const float4* pr = (const float4*)(sre + specbase + (size_t)k * FRAMES) + 2 * h;
        const float4* pi = (const float4*)(sim + specbase + (size_t)k * FRAMES) + 2 * h;
        float4 r0 = pr[0], r1 = pr[1];
        float4 i0 = pi[0], i1 = pi[1];
        float re[8] = {r0.x, r0.y, r0.z, r0.w, r1.x, r1.y, r1.z, r1.w};
        float im[8] = {i0.x, i0.y, i0.z, i0.w, i1.x, i1.y, i1.z, i1.w};
        if (k == 0) { im[0]=im[1]=im[2]=im[3]=im[4]=im[5]=im[6]=im[7]=0.0f; }
#pragma unroll
        for (int q = 0; q < 8; q++)
            buf[(8 * h + q) * FPITCH + k] = make_float2(re[q], im[q]);
    }
    if (tid < 2) {                      // Nyquist bin 512, imag dropped
        const int h = tid;
        const float4* pr = (const float4*)(sre + specbase + (size_t)512 * FRAMES) + 2 * h;
        float4 r0 = pr[0], r1 = pr[1];
        float re[8] = {r0.x, r0.y, r0.z, r0.w, r1.x, r1.y, r1.z, r1.w};
#pragma unroll
        for (int q = 0; q < 8; q++)
            buf[(8 * h + q) * FPITCH + 512] = make_float2(re[q], 0.0f);
    }
    __syncthreads();

    const int f = tid >> 6;             // frame within block (0..15)
    const int t = tid & 63;             // lane within frame
    float2* const Bf = buf + f * FPITCH;

    // ---- Pack: Z[k] = (S[k]+conj(S[512-k])) + i*w^k*(S[k]-conj(S[512-k])) --
    float2 v[8];
    {
        const float2 wt = ctw1[t];
        const float C16R[8] = { 1.0f, 0.92387953251128674f, 0.70710678118654752f,
                                0.38268343236508977f, 0.0f, -0.38268343236508977f,
                               -0.70710678118654752f, -0.92387953251128674f };
        const float C16I[8] = { 0.0f, 0.38268343236508977f, 0.70710678118654752f,
                                0.92387953251128674f, 1.0f, 0.92387953251128674f,
                                0.70710678118654752f, 0.38268343236508977f };
#pragma unroll
        for (int g = 0; g < 8; g++) {
            const int k = t + 64 * g;
            float2 A  = Bf[k];
            float2 Bc = Bf[512 - k];
            float Ur = A.x + Bc.x, Ui = A.y - Bc.y;
            float Vr = A.x - Bc.x, Vi = A.y + Bc.y;
            float wr = wt.x * C16R[g] - wt.y * C16I[g];
            float wi = wt.x * C16I[g] + wt.y * C16R[g];
            v[g] = make_float2(Ur - wr*Vi - wi*Vr,
                               Ui + wr*Vr - wi*Vi);
        }
    }
    __syncthreads();

    // ---- Stage 1: store at t + 72a -----------------------------------------
    ifft8(v);
#pragma unroll
    for (int a = 0; a < 8; a++)
        Bf[t + 72 * a] = v[a];
    __syncthreads();

    // ---- Stage 2: load alpha+8be+72a, twiddle, ifft8, store a+8bb+66alpha --
    {
        const int alpha = t & 7, a = t >> 3;
#pragma unroll
        for (int be = 0; be < 8; be++)
            v[be] = Bf[alpha + 8 * be + 72 * a];
        apply_twiddle_chain(v, ctw2[a]);        // w = e^{+2pi i a/64}
        __syncthreads();
        ifft8(v);
#pragma unroll
        for (int bb = 0; bb < 8; bb++)
            Bf[a + 8 * bb + 66 * alpha] = v[bb];
    }
    __syncthreads();

    // ---- Stage 3: load t + 66alpha, twiddle, ifft8 --------------------------
    {
#pragma unroll
        for (int al = 0; al < 8; al++)
            v[al] = Bf[t + 66 * al];
        apply_twiddle_chain(v, ctw3[t]);        // w = e^{+2pi i t/512}
        ifft8(v);          // v[c] = 1024 * z[t + 64c]
    }
    __syncthreads();       // all stage-3 smem reads done; buf reusable

    // ---- Unpack + window into smem frame buffer (pitch 1032 floats) --------
    float* const frb = (float*)buf;
#pragma unroll
    for (int c = 0; c < 8; c++) {
        const int n = t + 64 * c;                   // 0..511
        float2 w2 = *(const float2*)(win + 2 * n);
        *(float2*)(frb + f * 1032 + 2 * n) =
            make_float2(v[c].x * w2.x * (1.0f / 1024.0f),
                        v[c].y * w2.y * (1.0f / 1024.0f));
    }
    __syncthreads();

    // ---- In-smem overlap-add over the block's 16 frames ---------------------
    const float ENV_INV = 2.0f / 3.0f;
    float* outb = out + (size_t)b * OUTLEN;
    const int nbase = p * SPAN;

    // Interior: j in [HALO, SPAN) — always exactly 4 taps, env == 1.5 exact.
#pragma unroll 1
    for (int j = tid + HALO; j < SPAN; j += 1024) {
        const int mb  = (j >> 8) - 3;
        const int off = j - (mb << 8);              // 768..1023
        const float* base = frb + mb * 1032 + off;
        float acc = base[0] + base[1032 - 256] + base[2064 - 512] + base[3096 - 768];
        outb[nbase + j - PAD] = acc * ENV_INV;
    }

    // Edges: head j = tid in [0,HALO), tail j = SPAN + tid (tid < HALO).
    if (tid < HALO) {
#pragma unroll
        for (int e = 0; e < 2; e++) {
            const int j = e ? (SPAN + tid) : tid;
            int fhi = j >> 8;         if (fhi > FPB - 1) fhi = FPB - 1;
            int flo = (j - 768) >> 8; if (flo < 0) flo = 0;
            float acc = 0.0f;
            for (int m = flo; m <= fhi; m++)
                acc += frb[m * 1032 + j - (m << 8)];

            const int n = nbase + j;
            const int o = n - PAD;
            if ((p == 0 && !e) || (p == BPB - 1 && e)) {
                // true batch edge: compute env from the window
                int Mhi = n >> 8;         if (Mhi > FRAMES - 1) Mhi = FRAMES - 1;
                int Mlo = (n - 768) >> 8; if (Mlo < 0) Mlo = 0;
                float env = 0.0f;
                for (int m = Mlo; m <= Mhi; m++) {
                    const float w = win[n - (m << 8)];
                    env += w * w;
                }
                if (o >= 0 && o < OUTLEN)
                    atomicAdd(&outb[o], acc / env);
            } else {
                // interior block boundary: 4 taps globally -> env == 1.5
                atomicAdd(&outb[o], acc * ENV_INV);
            }
        }
    }
}

// ---------------------------------------------------------------------------
extern "C" void kernel_launch(void* const* d_in, const int* in_sizes, int n_in,
                              void* d_out, int out_size)
{
    const float* sre = (const float*)d_in[0];
    const float* sim = (const float*)d_in[1];
    const float* win = (const float*)d_in[2];
    float* out = (float*)d_out;

    const int smem = FPB * FPITCH * (int)sizeof(float2);   // 72,832 B
    cudaFuncSetAttribute(istft_fused_kernel,
                         cudaFuncAttributeMaxDynamicSharedMemorySize, smem);

    prep_kernel<<<NWIN, 192>>>(out);
    istft_fused_kernel<<<BATCH * FRAMES / FPB, 1024, smem>>>(sre, sim, win, out);
}

// round 10
// speedup vs baseline: 1.6134x; 1.1853x over previous
#include <cuda_runtime.h>

#define NFFT    1024
#define FREQ    513
#define FRAMES  2048
#define BATCH   16
#define HOP     256
#define PAD     384
#define OUTLEN  524288          // (2047*256 + 1024) - 2*384 == 2^19
#define FPB     16              // frames per block
#define FPITCH  569             // per-frame smem pitch (float2)
#define BPB     128             // blocks per batch (2048/16)
#define SPAN    4096            // samples advanced per block (FPB*HOP)
#define HALO    768
#define NWIN    (BATCH * (BPB + 1))    // halo windows to zero

__device__ float2 g_tw[1024];   // e^{+2*pi*i*j/1024}

// Packed f32x2 add/sub (FADD2 path on sm_103a; bitwise identical to scalar).
__device__ __forceinline__ float2 cadd(float2 a, float2 b){
    float2 r;
    asm("add.rn.f32x2 %0, %1, %2;"
        : "=l"(reinterpret_cast<unsigned long long&>(r))
        : "l"(reinterpret_cast<const unsigned long long&>(a)),
          "l"(reinterpret_cast<const unsigned long long&>(b)));
    return r;
}
__device__ __forceinline__ float2 csub(float2 a, float2 b){
    float2 r;
    asm("sub.rn.f32x2 %0, %1, %2;"
        : "=l"(reinterpret_cast<unsigned long long&>(r))
        : "l"(reinterpret_cast<const unsigned long long&>(a)),
          "l"(reinterpret_cast<const unsigned long long&>(b)));
    return r;
}
__device__ __forceinline__ float2 cmul(float2 a, float2 b){
    return make_float2(fmaf(a.x, b.x, -a.y*b.y), fmaf(a.x, b.y, a.y*b.x));
}
__device__ __forceinline__ float2 mul_i(float2 a){return make_float2(-a.y, a.x);}

// In-place 8-point inverse DFT: y[n] = sum_m v[m] e^{+2*pi*i*m*n/8}
__device__ __forceinline__ void ifft8(float2* v){
    float2 e2a = cadd(v[0], v[4]);
    float2 e2b = csub(v[0], v[4]);
    float2 o2a = cadd(v[2], v[6]);
    float2 o2b = csub(v[2], v[6]);
    float2 E0 = cadd(e2a, o2a);
    float2 E2 = csub(e2a, o2a);
    float2 io2b = mul_i(o2b);
    float2 E1 = cadd(e2b, io2b);
    float2 E3 = csub(e2b, io2b);
    float2 p2a = cadd(v[1], v[5]);
    float2 p2b = csub(v[1], v[5]);
    float2 q2a = cadd(v[3], v[7]);
    float2 q2b = csub(v[3], v[7]);
    float2 O0 = cadd(p2a, q2a);
    float2 O2 = csub(p2a, q2a);
    float2 iq2b = mul_i(q2b);
    float2 O1 = cadd(p2b, iq2b);
    float2 O3 = csub(p2b, iq2b);
    const float C = 0.70710678118654752440f;
    float2 w1O1 = make_float2(C*(O1.x - O1.y),  C*(O1.x + O1.y));
    float2 w3O3 = make_float2(-C*(O3.x + O3.y), C*(O3.x - O3.y));
    float2 iO2  = mul_i(O2);
    v[0]=cadd(E0,O0);   v[4]=csub(E0,O0);
    v[1]=cadd(E1,w1O1); v[5]=csub(E1,w1O1);
    v[2]=cadd(E2,iO2);  v[6]=csub(E2,iO2);
    v[3]=cadd(E3,w3O3); v[7]=csub(E3,w3O3);
}

// Apply w^1..w^7 to v[1..7] via register power chain.
__device__ __forceinline__ void apply_twiddle_chain(float2* v, float2 w1){
    float2 w2 = cmul(w1, w1);
    float2 w3 = cmul(w2, w1);
    float2 w4 = cmul(w2, w2);
    float2 w5 = cmul(w3, w2);
    float2 w6 = cmul(w3, w3);
    float2 w7 = cmul(w4, w3);
    v[1] = cmul(v[1], w1);
    v[2] = cmul(v[2], w2);
    v[3] = cmul(v[3], w3);
    v[4] = cmul(v[4], w4);
    v[5] = cmul(v[5], w5);
    v[6] = cmul(v[6], w6);
    v[7] = cmul(v[7], w7);
}

// ---------------------------------------------------------------------------
// Prep kernel: one block zeroes one 768-float halo window (192 float4 stores).
// Block 0 additionally builds the twiddle table.
// ---------------------------------------------------------------------------
__global__ __launch_bounds__(192) void prep_kernel(float* __restrict__ out){
    const int r = blockIdx.x;                 // 0 .. NWIN-1
    if (r == 0) {
        for (int j = threadIdx.x; j < 1024; j += 192) {
            float s, c;
            sincosf((float)j * 6.13592315154256491887e-3f, &s, &c); // 2*pi/1024
            g_tw[j] = make_float2(c, s);
        }
    }
    const int b = r / (BPB + 1);
    const int p = r % (BPB + 1);
    const int o4start = (p * SPAN - PAD) >> 2;
    const int o4 = o4start + threadIdx.x;
    if (o4 >= 0 && o4 < OUTLEN / 4) {
        float4* dst = (float4*)(out + (size_t)b * OUTLEN);
        dst[o4] = make_float4(0.f, 0.f, 0.f, 0.f);
    }
}

// ---------------------------------------------------------------------------
// Fused kernel: Hermitian pack fused into the GLOBAL loader (Z written once,
// read once), radix-8^3 on 512-pt complex, window, in-smem overlap-add.
// 1024 threads = 16 frames x 64 threads.
// ---------------------------------------------------------------------------
__global__ __launch_bounds__(1024, 2) void istft_fused_kernel(
    const float* __restrict__ sre,
    const float* __restrict__ sim,
    const float* __restrict__ win,
    float* __restrict__ out)
{
    __shared__ float2 ctw2[8];          // e^{+2pi i a/64}
    __shared__ float2 ctw3[64];         // e^{+2pi i t/512}
    extern __shared__ float2 buf[];     // [FPB * FPITCH] float2; reused for OLA

    const int tid = threadIdx.x;

    if (tid < 64) {
        ctw3[tid] = g_tw[2 * tid];
        if (tid < 8) ctw2[tid] = g_tw[16 * tid];
    }

    // ---- Load spectrum pair (k, 512-k) + Hermitian pack -> Z in smem -------
    const int gf0 = blockIdx.x * FPB;
    const int b   = gf0 >> 11;               // batch
    const int p   = blockIdx.x & (BPB - 1);  // block within batch
    const int fr  = gf0 & (FRAMES - 1);
    const size_t specbase = (size_t)b * FREQ * FRAMES + fr;
    {
        const int pp = tid >> 2;        // pair index 0..255
        const int q  = tid & 3;         // frame quad: frames 4q..4q+3
        if (pp == 0) {
            // k=0 uses bins 0 (im==0) and 512 (im dropped); k=256 self-mirror.
            float4 r0   = ((const float4*)(sre + specbase))[q];
            float4 r512 = ((const float4*)(sre + specbase + (size_t)512 * FRAMES))[q];
            float4 r256 = ((const float4*)(sre + specbase + (size_t)256 * FRAMES))[q];
            float4 i256 = ((const float4*)(sim + specbase + (size_t)256 * FRAMES))[q];
            const float a0[4]  = {r0.x, r0.y, r0.z, r0.w};
            const float b0[4]  = {r512.x, r512.y, r512.z, r512.w};
            const float cr[4]  = {r256.x, r256.y, r256.z, r256.w};
            const float ci[4]  = {i256.x, i256.y, i256.z, i256.w};
#pragma unroll
            for (int j = 0; j < 4; j++) {
                float2* Zf = buf + (4 * q + j) * FPITCH;
                Zf[0]   = make_float2(a0[j] + b0[j], a0[j] - b0[j]);
                Zf[256] = make_float2(2.0f * cr[j], -2.0f * ci[j]);
            }
        } else {
            const float2 w = g_tw[pp];  // e^{+2pi i pp/1024}
            float4 ar4 = ((const float4*)(sre + specbase + (size_t)pp * FRAMES))[q];
            float4 ai4 = ((const float4*)(sim + specbase + (size_t)pp * FRAMES))[q];
            float4 br4 = ((const float4*)(sre + specbase + (size_t)(512 - pp) * FRAMES))[q];
            float4 bi4 = ((const float4*)(sim + specbase + (size_t)(512 - pp) * FRAMES))[q];
            const float ar[4] = {ar4.x, ar4.y, ar4.z, ar4.w};
            const float ai[4] = {ai4.x, ai4.y, ai4.z, ai4.w};
            const float br[4] = {br4.x, br4.y, br4.z, br4.w};
            const float bi[4] = {bi4.x, bi4.y, bi4.z, bi4.w};
#pragma unroll
            for (int j = 0; j < 4; j++) {
                const float Ur = ar[j] + br[j], Ui = ai[j] - bi[j];
                const float Vr = ar[j] - br[j], Vi = ai[j] + bi[j];
                const float Xr = w.x * Vr - w.y * Vi;
                const float Xi = w.x * Vi + w.y * Vr;
                float2* Zf = buf + (4 * q + j) * FPITCH;
                Zf[pp]       = make_float2(Ur - Xi,  Ui + Xr);
                Zf[512 - pp] = make_float2(Ur + Xi, -Ui + Xr);
            }
        }
    }
    __syncthreads();

    const int f = tid >> 6;             // frame within block (0..15)
    const int t = tid & 63;             // lane within frame
    float2* const Bf = buf + f * FPITCH;

    // ---- Stage 1: read Z[t+64g], ifft8, store at t + 72a -------------------
    float2 v[8];
#pragma unroll
    for (int g = 0; g < 8; g++)
        v[g] = Bf[t + 64 * g];
    __syncthreads();
    ifft8(v);
#pragma unroll
    for (int a = 0; a < 8; a++)
        Bf[t + 72 * a] = v[a];
    __syncthreads();

    // ---- Stage 2: load alpha+8be+72a, twiddle, ifft8, store a+8bb+66alpha --
    {
        const int alpha = t & 7, a = t >> 3;
#pragma unroll
        for (int be = 0; be < 8; be++)
            v[be] = Bf[alpha + 8 * be + 72 * a];
        apply_twiddle_chain(v, ctw2[a]);        // w = e^{+2pi i a/64}
        __syncthreads();
        ifft8(v);
#pragma unroll
        for (int bb = 0; bb < 8; bb++)
            Bf[a + 8 * bb + 66 * alpha] = v[bb];
    }
    __syncthreads();

    // ---- Stage 3: load t + 66alpha, twiddle, ifft8 --------------------------
    {
#pragma unroll
        for (int al = 0; al < 8; al++)
            v[al] = Bf[t + 66 * al];
        apply_twiddle_chain(v, ctw3[t]);        // w = e^{+2pi i t/512}
        ifft8(v);          // v[c] = 1024 * z[t + 64c]
    }
    __syncthreads();       // all stage-3 smem reads done; buf reusable

    // ---- Unpack + window into smem frame buffer (pitch 1032 floats) --------
    float* const frb = (float*)buf;
#pragma unroll
    for (int c = 0; c < 8; c++) {
        const int n = t + 64 * c;                   // 0..511
        float2 w2 = *(const float2*)(win + 2 * n);
        *(float2*)(frb + f * 1032 + 2 * n) =
            make_float2(v[c].x * w2.x * (1.0f / 1024.0f),
                        v[c].y * w2.y * (1.0f / 1024.0f));
    }
    __syncthreads();

    // ---- In-smem overlap-add over the block's 16 frames ---------------------
    const float ENV_INV = 2.0f / 3.0f;
    float* outb = out + (size_t)b * OUTLEN;
    const int nbase = p * SPAN;

    // Interior: j in [HALO, SPAN), float2-vectorized; exactly 4 taps, env 1.5.
#pragma unroll 1
    for (int j = 2 * tid + HALO; j < SPAN; j += 2048) {
        const int mb  = (j >> 8) - 3;
        const int off = j - (mb << 8);              // 768..1023, even
        const float* base = frb + mb * 1032 + off;
        float2 t0 = *(const float2*)(base);
        float2 t1 = *(const float2*)(base + 776);
        float2 t2 = *(const float2*)(base + 1552);
        float2 t3 = *(const float2*)(base + 2328);
        float2 r = make_float2((t0.x + t1.x + t2.x + t3.x) * ENV_INV,
                               (t0.y + t1.y + t2.y + t3.y) * ENV_INV);
        *(float2*)(outb + nbase + j - PAD) = r;
    }

    // Edges: head j = tid in [0,HALO), tail j = SPAN + tid (tid < HALO).
    if (tid < HALO) {
#pragma unroll
        for (int e = 0; e < 2; e++) {
            const int j = e ? (SPAN + tid) : tid;
            int fhi = j >> 8;         if (fhi > FPB - 1) fhi = FPB - 1;
            int flo = (j - 768) >> 8; if (flo < 0) flo = 0;
            float acc = 0.0f;
            for (int m = flo; m <= fhi; m++)
                acc += frb[m * 1032 + j - (m << 8)];

            const int n = nbase + j;
            const int o = n - PAD;
            if ((p == 0 && !e) || (p == BPB - 1 && e)) {
                // true batch edge: compute env from the window
                int Mhi = n >> 8;         if (Mhi > FRAMES - 1) Mhi = FRAMES - 1;
                int Mlo = (n - 768) >> 8; if (Mlo < 0) Mlo = 0;
                float env = 0.0f;
                for (int m = Mlo; m <= Mhi; m++) {
                    const float w = win[n - (m << 8)];
                    env += w * w;
                }
                if (o >= 0 && o < OUTLEN)
                    atomicAdd(&outb[o], acc / env);
            } else {
                // interior block boundary: 4 taps globally -> env == 1.5
                atomicAdd(&outb[o], acc * ENV_INV);
            }
        }
    }
}

// ---------------------------------------------------------------------------
extern "C" void kernel_launch(void* const* d_in, const int* in_sizes, int n_in,
                              void* d_out, int out_size)
{
    const float* sre = (const float*)d_in[0];
    const float* sim = (const float*)d_in[1];
    const float* win = (const float*)d_in[2];
    float* out = (float*)d_out;

    const int smem = FPB * FPITCH * (int)sizeof(float2);   // 72,832 B
    cudaFuncSetAttribute(istft_fused_kernel,
                         cudaFuncAttributeMaxDynamicSharedMemorySize, smem);

    prep_kernel<<<NWIN, 192>>>(out);
    istft_fused_kernel<<<BATCH * FRAMES / FPB, 1024, smem>>>(sre, sim, win, out);
}

// round 12
// speedup vs baseline: 1.6723x; 1.0365x over previous
#include <cuda_runtime.h>

#define NFFT    1024
#define FREQ    513
#define FRAMES  2048
#define BATCH   16
#define HOP     256
#define PAD     384
#define OUTLEN  524288          // (2047*256 + 1024) - 2*384 == 2^19
#define FPB     16              // frames per block
#define FPITCH  569             // per-frame FFT pitch (float2)
#define OPITCHF 1140            // per-frame OLA pitch (floats), mult of 4
#define BPB     128             // blocks per batch (2048/16)
#define SPAN    4096            // samples advanced per block (FPB*HOP)
#define HALO    768
#define NWIN    (BATCH * (BPB + 1))    // halo windows to zero

__device__ float2 g_tw[1024];   // e^{+2*pi*i*j/1024}

// Frame-pair barrier: frames 2g,2g+1 share named barrier id 1+g (ids 1..8,
// id 0 reserved for __syncthreads), 128 threads = 4 warps.
__device__ __forceinline__ void barf(int f){
    asm volatile("bar.sync %0, 128;" :: "r"(1 + (f >> 1)) : "memory");
}

// Packed f32x2 add/sub (FADD2 path on sm_103a; bitwise identical to scalar).
__device__ __forceinline__ float2 cadd(float2 a, float2 b){
    float2 r;
    asm("add.rn.f32x2 %0, %1, %2;"
        : "=l"(reinterpret_cast<unsigned long long&>(r))
        : "l"(reinterpret_cast<const unsigned long long&>(a)),
          "l"(reinterpret_cast<const unsigned long long&>(b)));
    return r;
}
__device__ __forceinline__ float2 csub(float2 a, float2 b){
    float2 r;
    asm("sub.rn.f32x2 %0, %1, %2;"
        : "=l"(reinterpret_cast<unsigned long long&>(r))
        : "l"(reinterpret_cast<const unsigned long long&>(a)),
          "l"(reinterpret_cast<const unsigned long long&>(b)));
    return r;
}
__device__ __forceinline__ float2 cmul(float2 a, float2 b){
    return make_float2(fmaf(a.x, b.x, -a.y*b.y), fmaf(a.x, b.y, a.y*b.x));
}
__device__ __forceinline__ float2 mul_i(float2 a){return make_float2(-a.y, a.x);}

// In-place 8-point inverse DFT: y[n] = sum_m v[m] e^{+2*pi*i*m*n/8}
__device__ __forceinline__ void ifft8(float2* v){
    float2 e2a = cadd(v[0], v[4]);
    float2 e2b = csub(v[0], v[4]);
    float2 o2a = cadd(v[2], v[6]);
    float2 o2b = csub(v[2], v[6]);
    float2 E0 = cadd(e2a, o2a);
    float2 E2 = csub(e2a, o2a);
    float2 io2b = mul_i(o2b);
    float2 E1 = cadd(e2b, io2b);
    float2 E3 = csub(e2b, io2b);
    float2 p2a = cadd(v[1], v[5]);
    float2 p2b = csub(v[1], v[5]);
    float2 q2a = cadd(v[3], v[7]);
    float2 q2b = csub(v[3], v[7]);
    float2 O0 = cadd(p2a, q2a);
    float2 O2 = csub(p2a, q2a);
    float2 iq2b = mul_i(q2b);
    float2 O1 = cadd(p2b, iq2b);
    float2 O3 = csub(p2b, iq2b);
    const float C = 0.70710678118654752440f;
    float2 w1O1 = make_float2(C*(O1.x - O1.y),  C*(O1.x + O1.y));
    float2 w3O3 = make_float2(-C*(O3.x + O3.y), C*(O3.x - O3.y));
    float2 iO2  = mul_i(O2);
    v[0]=cadd(E0,O0);   v[4]=csub(E0,O0);
    v[1]=cadd(E1,w1O1); v[5]=csub(E1,w1O1);
    v[2]=cadd(E2,iO2);  v[6]=csub(E2,iO2);
    v[3]=cadd(E3,w3O3); v[7]=csub(E3,w3O3);
}

// Apply w^1..w^7 to v[1..7] via register power chain.
__device__ __forceinline__ void apply_twiddle_chain(float2* v, float2 w1){
    float2 w2 = cmul(w1, w1);
    float2 w3 = cmul(w2, w1);
    float2 w4 = cmul(w2, w2);
    float2 w5 = cmul(w3, w2);
    float2 w6 = cmul(w3, w3);
    float2 w7 = cmul(w4, w3);
    v[1] = cmul(v[1], w1);
    v[2] = cmul(v[2], w2);
    v[3] = cmul(v[3], w3);
    v[4] = cmul(v[4], w4);
    v[5] = cmul(v[5], w5);
    v[6] = cmul(v[6], w6);
    v[7] = cmul(v[7], w7);
}

// ---------------------------------------------------------------------------
// Prep kernel: one block zeroes one 768-float halo window (192 float4 stores).
// Block 0 additionally builds the twiddle table.
// ---------------------------------------------------------------------------
__global__ __launch_bounds__(192) void prep_kernel(float* __restrict__ out){
    const int r = blockIdx.x;                 // 0 .. NWIN-1
    if (r == 0) {
        for (int j = threadIdx.x; j < 1024; j += 192) {
            float s, c;
            sincosf((float)j * 6.13592315154256491887e-3f, &s, &c); // 2*pi/1024
            g_tw[j] = make_float2(c, s);
        }
    }
    const int b = r / (BPB + 1);
    const int p = r % (BPB + 1);
    const int o4start = (p * SPAN - PAD) >> 2;
    const int o4 = o4start + threadIdx.x;
    if (o4 >= 0 && o4 < OUTLEN / 4) {
        float4* dst = (float4*)(out + (size_t)b * OUTLEN);
        dst[o4] = make_float4(0.f, 0.f, 0.f, 0.f);
    }
}

// ---------------------------------------------------------------------------
// Fused kernel: Hermitian pack in the global loader, radix-8^3 on 512-pt
// complex with frame-pair named barriers (128-thread scope), window, in-smem
// overlap-add. 1024 threads = 16 frames x 64 threads. 2 full syncs only.
// ---------------------------------------------------------------------------
__global__ __launch_bounds__(1024, 2) void istft_fused_kernel(
    const float* __restrict__ sre,
    const float* __restrict__ sim,
    const float* __restrict__ win,
    float* __restrict__ out)
{
    __shared__ float2 ctw2[8];          // e^{+2pi i a/64}
    __shared__ float2 ctw3[64];         // e^{+2pi i t/512}
    extern __shared__ float2 buf[];     // [FPB * 570] float2; reused for OLA

    const int tid = threadIdx.x;

    if (tid < 64) {
        ctw3[tid] = g_tw[2 * tid];
        if (tid < 8) ctw2[tid] = g_tw[16 * tid];
    }

    // ---- Load spectrum pair (k, 512-k) + Hermitian pack -> Z in smem -------
    const int gf0 = blockIdx.x * FPB;
    const int b   = gf0 >> 11;               // batch
    const int p   = blockIdx.x & (BPB - 1);  // block within batch
    const int fr  = gf0 & (FRAMES - 1);
    const size_t specbase = (size_t)b * FREQ * FRAMES + fr;
    {
        const int pp = tid >> 2;        // pair index 0..255
        const int q  = tid & 3;         // frame quad: frames 4q..4q+3
        if (pp == 0) {
            float4 r0   = ((const float4*)(sre + specbase))[q];
            float4 r512 = ((const float4*)(sre + specbase + (size_t)512 * FRAMES))[q];
            float4 r256 = ((const float4*)(sre + specbase + (size_t)256 * FRAMES))[q];
            float4 i256 = ((const float4*)(sim + specbase + (size_t)256 * FRAMES))[q];
            const float a0[4]  = {r0.x, r0.y, r0.z, r0.w};
            const float b0[4]  = {r512.x, r512.y, r512.z, r512.w};
            const float cr[4]  = {r256.x, r256.y, r256.z, r256.w};
            const float ci[4]  = {i256.x, i256.y, i256.z, i256.w};
#pragma unroll
            for (int j = 0; j < 4; j++) {
                float2* Zf = buf + (4 * q + j) * FPITCH;
                Zf[0]   = make_float2(a0[j] + b0[j], a0[j] - b0[j]);
                Zf[256] = make_float2(2.0f * cr[j], -2.0f * ci[j]);
            }
        } else {
            const float2 w = g_tw[pp];  // e^{+2pi i pp/1024}
            float4 ar4 = ((const float4*)(sre + specbase + (size_t)pp * FRAMES))[q];
            float4 ai4 = ((const float4*)(sim + specbase + (size_t)pp * FRAMES))[q];
            float4 br4 = ((const float4*)(sre + specbase + (size_t)(512 - pp) * FRAMES))[q];
            float4 bi4 = ((const float4*)(sim + specbase + (size_t)(512 - pp) * FRAMES))[q];
            const float ar[4] = {ar4.x, ar4.y, ar4.z, ar4.w};
            const float ai[4] = {ai4.x, ai4.y, ai4.z, ai4.w};
            const float br[4] = {br4.x, br4.y, br4.z, br4.w};
            const float bi[4] = {bi4.x, bi4.y, bi4.z, bi4.w};
#pragma unroll
            for (int j = 0; j < 4; j++) {
                const float Ur = ar[j] + br[j], Ui = ai[j] - bi[j];
                const float Vr = ar[j] - br[j], Vi = ai[j] + bi[j];
                const float Xr = w.x * Vr - w.y * Vi;
                const float Xi = w.x * Vi + w.y * Vr;
                float2* Zf = buf + (4 * q + j) * FPITCH;
                Zf[pp]       = make_float2(Ur - Xi,  Ui + Xr);
                Zf[512 - pp] = make_float2(Ur + Xi, -Ui + Xr);
            }
        }
    }
    __syncthreads();                    // FULL: loader crosses frames

    const int f = tid >> 6;             // frame within block (0..15)
    const int t = tid & 63;             // lane within frame
    float2* const Bf = buf + f * FPITCH;

    // ---- Stage 1: read Z[t+64g], ifft8, store at t + 72a -------------------
    float2 v[8];
#pragma unroll
    for (int g = 0; g < 8; g++)
        v[g] = Bf[t + 64 * g];
    barf(f);
    ifft8(v);
#pragma unroll
    for (int a = 0; a < 8; a++)
        Bf[t + 72 * a] = v[a];
    barf(f);

    // ---- Stage 2: load alpha+8be+72a, twiddle, ifft8, store a+8bb+66alpha --
    {
        const int alpha = t & 7, a = t >> 3;
#pragma unroll
        for (int be = 0; be < 8; be++)
            v[be] = Bf[alpha + 8 * be + 72 * a];
        apply_twiddle_chain(v, ctw2[a]);        // w = e^{+2pi i a/64}
        barf(f);
        ifft8(v);
#pragma unroll
        for (int bb = 0; bb < 8; bb++)
            Bf[a + 8 * bb + 66 * alpha] = v[bb];
    }
    barf(f);

    // ---- Stage 3: load t + 66alpha, twiddle, ifft8 --------------------------
    {
#pragma unroll
        for (int al = 0; al < 8; al++)
            v[al] = Bf[t + 66 * al];
        apply_twiddle_chain(v, ctw3[t]);        // w = e^{+2pi i t/512}
        ifft8(v);          // v[c] = 1024 * z[t + 64c]
    }
    barf(f);               // frame-pair's stage-3 reads done; unpack regions
                           // don't cross frame FFT regions (1140 vs 1138 pitch)

    // ---- Unpack + window into smem frame buffer (pitch OPITCHF floats) ------
    float* const frb = (float*)buf;
#pragma unroll
    for (int c = 0; c < 8; c++) {
        const int n = t + 64 * c;                   // 0..511
        float2 w2 = *(const float2*)(win + 2 * n);
        *(float2*)(frb + f * OPITCHF + 2 * n) =
            make_float2(v[c].x * w2.x * (1.0f / 1024.0f),
                        v[c].y * w2.y * (1.0f / 1024.0f));
    }
    __syncthreads();                    // FULL: OLA reads cross frames

    // ---- In-smem overlap-add over the block's 16 frames ---------------------
    const float ENV_INV = 2.0f / 3.0f;
    float* outb = out + (size_t)b * OUTLEN;
    const int nbase = p * SPAN;

    // Interior: j in [HALO, SPAN), one float4 per thread (832 tasks).
    if (tid < (SPAN - HALO) / 4) {
        const int j   = 4 * tid + HALO;             // 768..4092
        const int mb  = (j >> 8) - 3;
        const int off = j - (mb << 8);              // 768..1020, mult of 4
        const float* base = frb + mb * OPITCHF + off;
        float4 t0 = *(const float4*)(base);
        float4 t1 = *(const float4*)(base + (OPITCHF - 256));
        float4 t2 = *(const float4*)(base + 2 * (OPITCHF - 256));
        float4 t3 = *(const float4*)(base + 3 * (OPITCHF - 256));
        float4 r;
        r.x = (t0.x + t1.x + t2.x + t3.x) * ENV_INV;
        r.y = (t0.y + t1.y + t2.y + t3.y) * ENV_INV;
        r.z = (t0.z + t1.z + t2.z + t3.z) * ENV_INV;
        r.w = (t0.w + t1.w + t2.w + t3.w) * ENV_INV;
        *(float4*)(outb + nbase + j - PAD) = r;
    }

    // Edges: 1536 tasks spread over 1024 threads.
#pragma unroll 1
    for (int tau = tid; tau < 2 * HALO; tau += 1024) {
        const int e = (tau >= HALO);
        const int j = e ? (SPAN + tau - HALO) : tau;
        int fhi = j >> 8;         if (fhi > FPB - 1) fhi = FPB - 1;
        int flo = (j - 768) >> 8; if (flo < 0) flo = 0;
        float acc = 0.0f;
        for (int m = flo; m <= fhi; m++)
            acc += frb[m * OPITCHF + j - (m << 8)];

        const int n = nbase + j;
        const int o = n - PAD;
        if ((p == 0 && !e) || (p == BPB - 1 && e)) {
            // true batch edge: compute env from the window
            int Mhi = n >> 8;         if (Mhi > FRAMES - 1) Mhi = FRAMES - 1;
            int Mlo = (n - 768) >> 8; if (Mlo < 0) Mlo = 0;
            float env = 0.0f;
            for (int m = Mlo; m <= Mhi; m++) {
                const float w = win[n - (m << 8)];
                env += w * w;
            }
            if (o >= 0 && o < OUTLEN)
                atomicAdd(&outb[o], acc / env);
        } else {
            // interior block boundary: 4 taps globally -> env == 1.5
            atomicAdd(&outb[o], acc * ENV_INV);
        }
    }
}

// ---------------------------------------------------------------------------
extern "C" void kernel_launch(void* const* d_in, const int* in_sizes, int n_in,
                              void* d_out, int out_size)
{
    const float* sre = (const float*)d_in[0];
    const float* sim = (const float*)d_in[1];
    const float* win = (const float*)d_in[2];
    float* out = (float*)d_out;

    const int smem = FPB * 570 * (int)sizeof(float2);   // 72,960 B
    cudaFuncSetAttribute(istft_fused_kernel,
                         cudaFuncAttributeMaxDynamicSharedMemorySize, smem);

    prep_kernel<<<NWIN, 192>>>(out);
    istft_fused_kernel<<<BATCH * FRAMES / FPB, 1024, smem>>>(sre, sim, win, out);
}